// round 16
// baseline (speedup 1.0000x reference)
#include <cuda_runtime.h>
#include <math.h>

#define TS 32
#define NT 256
#define IN_DIM 40
#define IN_STR 44
#define TMP_STR 37
#define BLUR_STR 38   // even: 8B-aligned column pairs
#define BLUR_DIM 36
#define GM_DIM 34
#define GM_STR 36     // even: 8B-aligned float2 rows

#define IN_CH   (IN_DIM * IN_STR)     // 1760
#define TMP_CH  (IN_DIM * TMP_STR)    // 1480
#define BLUR_CH (BLUR_DIM * BLUR_STR) // 1368 (<= 1760, aliases s_in)

__global__ __launch_bounds__(NT) void canny_fused_kernel(
    const float* __restrict__ img, float* __restrict__ out,
    int H, int W)
{
    __shared__ __align__(16) float s_pool[3 * IN_CH];   // s_in[3]; aliased by s_blur[3]
    __shared__ __align__(16) float s_tmpa[3 * TMP_CH];
    __shared__ __align__(16) float s_gmag[GM_DIM * GM_STR];
    __shared__ int s_noff[8];

    const int tid = threadIdx.x;
    const int x0 = blockIdx.x * TS;
    const int y0 = blockIdx.y * TS;
    const int b  = blockIdx.z;

    // proven literals + pinned forms (R15 passed with these)
    const float G0 = 0.13533528f;   // exp(-2)
    const float G1 = 0.60653067f;   // exp(-0.5)

    if (tid < 8) {
        const int ddy[8] = {0, 1, 1, 1, 0, -1, -1, -1};
        const int ddx[8] = {1, 1, 0, -1, -1, -1, 0, 1};
        s_noff[tid] = ddy[tid] * GM_STR + ddx[tid];
    }

    // ---- fixed per-thread mappings (computed ONCE) ----
    const int rA0 = tid / 10, cA0 = (tid - rA0 * 10) * 4;
    const int uA1 = tid + NT;
    const int rA1 = uA1 / 10, cA1 = (uA1 - rA1 * 10) * 4;
    const int tB_r = tid / 6, tB_c0 = (tid - tB_r * 6) * 6;       // tid<240
    const int tC_rs = tid / 36, tC_c = tid - tC_rs * 36;          // tid<216
    const int tC_r0 = tC_rs * 6;
    // stage D: 204 threads = 12 three-row segments x 17 column pairs
    const int tD_pr = tid / 17, tD_pc = tid - tD_pr * 17;         // tid<204
    const int dcc  = tD_pc * 2;                                    // even column base
    const int r0   = tD_pr * 3;
    const int rend = (r0 + 3 < GM_DIM) ? (r0 + 3) : GM_DIM;

    const bool interior = (x0 >= 32) && (x0 <= 448) && (y0 >= 32) && (y0 <= 448);
    const float* base = img + ((size_t)b * 3) * H * W;
    const size_t HW = (size_t)H * W;

    float amag[2][3], agx[2][3], agy[2][3];

    // ================= stage A: load all 3 channels =================
    if (interior) {
        const float* g0 = base + (size_t)(y0 - 4) * W + (x0 - 4);
        #pragma unroll
        for (int c = 0; c < 3; ++c) {
            const float* gc = g0 + (size_t)c * HW;
            float* sc = s_pool + c * IN_CH;
            *(float4*)(&sc[rA0 * IN_STR + cA0]) = *(const float4*)(gc + (size_t)rA0 * W + cA0);
            if (tid < 144)
                *(float4*)(&sc[rA1 * IN_STR + cA1]) = *(const float4*)(gc + (size_t)rA1 * W + cA1);
        }
    } else {
        for (int c = 0; c < 3; ++c) {
            const float* gc = base + (size_t)c * HW;
            float* sc = s_pool + c * IN_CH;
            for (int i = tid; i < IN_DIM * IN_DIM; i += NT) {
                int r = i / IN_DIM, cc = i - r * IN_DIM;
                int gy = y0 - 4 + r, gx = x0 - 4 + cc;
                float v = 0.0f;
                if (gy >= 0 && gy < H && gx >= 0 && gx < W) v = gc[(size_t)gy * W + gx];
                sc[r * IN_STR + cc] = v;
            }
        }
    }
    __syncthreads();

    // ================= stage B: horizontal gaussian (rolling window, R15 text) =================
    if (tid < 240) {
        #pragma unroll
        for (int c = 0; c < 3; ++c) {
            const float* si = s_pool + c * IN_CH + tB_r * IN_STR;
            float* st = s_tmpa + c * TMP_CH + tB_r * TMP_STR;
            float w0 = si[tB_c0],     w1 = si[tB_c0 + 1], w2 = si[tB_c0 + 2];
            float w3 = si[tB_c0 + 3], w4 = si[tB_c0 + 4];
            #pragma unroll
            for (int j = 0; j < 6; ++j) {
                int cc = tB_c0 + j;
                float f1 = __fadd_rn(w0, w4);
                float f2 = __fadd_rn(w1, w3);
                st[cc] = __fadd_rn(__fmaf_rn(G0, f1, __fmul_rn(G1, f2)), w2);
                if (j < 5) {
                    float wn = si[cc + 5];
                    w0 = w1; w1 = w2; w2 = w3; w3 = w4; w4 = wn;
                }
            }
        }
    }
    __syncthreads();

    // ================= stage C: vertical gaussian (rolling window, R15 text) =================
    if (tid < 216) {
        if (interior) {
            #pragma unroll
            for (int c = 0; c < 3; ++c) {
                const float* st = s_tmpa + c * TMP_CH;
                float* sb = s_pool + c * BLUR_CH;
                int cc = tC_c;
                float w0 = st[(tC_r0 + 0) * TMP_STR + cc], w1 = st[(tC_r0 + 1) * TMP_STR + cc];
                float w2 = st[(tC_r0 + 2) * TMP_STR + cc], w3 = st[(tC_r0 + 3) * TMP_STR + cc];
                float w4 = st[(tC_r0 + 4) * TMP_STR + cc];
                #pragma unroll
                for (int j = 0; j < 6; ++j) {
                    int r = tC_r0 + j;
                    float f1 = __fadd_rn(w0, w4);
                    float f2 = __fadd_rn(w1, w3);
                    sb[r * BLUR_STR + cc] = __fadd_rn(__fmaf_rn(G0, f1, __fmul_rn(G1, f2)), w2);
                    if (j < 5) {
                        float wn = st[(r + 5) * TMP_STR + cc];
                        w0 = w1; w1 = w2; w2 = w3; w3 = w4; w4 = wn;
                    }
                }
            }
        } else {
            #pragma unroll
            for (int c = 0; c < 3; ++c) {
                const float* st = s_tmpa + c * TMP_CH;
                float* sb = s_pool + c * BLUR_CH;
                int cc = tC_c;
                float w0 = st[(tC_r0 + 0) * TMP_STR + cc], w1 = st[(tC_r0 + 1) * TMP_STR + cc];
                float w2 = st[(tC_r0 + 2) * TMP_STR + cc], w3 = st[(tC_r0 + 3) * TMP_STR + cc];
                float w4 = st[(tC_r0 + 4) * TMP_STR + cc];
                #pragma unroll
                for (int j = 0; j < 6; ++j) {
                    int r = tC_r0 + j;
                    int gy = y0 - 2 + r, gx = x0 - 2 + cc;
                    float v = 0.0f;
                    if (gy >= 0 && gy < H && gx >= 0 && gx < W) {
                        float f1 = __fadd_rn(w0, w4);
                        float f2 = __fadd_rn(w1, w3);
                        v = __fadd_rn(__fmaf_rn(G0, f1, __fmul_rn(G1, f2)), w2);
                    }
                    sb[r * BLUR_STR + cc] = v;
                    if (j < 5) {
                        float wn = st[(r + 5) * TMP_STR + cc];
                        w0 = w1; w1 = w2; w2 = w3; w3 = w4; w4 = wn;
                    }
                }
            }
        }
    }
    __syncthreads();

    // ================= stage D: sobel + |grad|, column-pair rolling 3x3 (R11-proven FP) =================
    if (tid < 204) {
        int cc = dcc;
        #pragma unroll
        for (int c = 0; c < 3; ++c) {
            const float* sb = s_pool + c * BLUR_CH;
            float2 T01 = *(const float2*)(&sb[r0 * BLUR_STR + cc]);
            float2 T23 = *(const float2*)(&sb[r0 * BLUR_STR + cc + 2]);
            float2 M01 = *(const float2*)(&sb[(r0 + 1) * BLUR_STR + cc]);
            float2 M23 = *(const float2*)(&sb[(r0 + 1) * BLUR_STR + cc + 2]);
            #pragma unroll
            for (int k = 0; k < 3; ++k) {
                int r = r0 + k;
                if (r < rend) {
                    float2 B01 = *(const float2*)(&sb[(r + 2) * BLUR_STR + cc]);
                    float2 B23 = *(const float2*)(&sb[(r + 2) * BLUR_STR + cc + 2]);
                    int gyp = y0 - 1 + r;
                    bool rowok = interior || (gyp >= 0 && gyp < H);
                    // column 0
                    {
                        float t0 = T01.x, t1 = T01.y, t2 = T23.x;
                        float m0 = M01.x,              m2 = M23.x;
                        float b0 = B01.x, b1 = B01.y, b2 = B23.x;
                        int gxp = x0 - 1 + cc;
                        float mag = 0.0f, gxv = 0.0f, gyv = 0.0f;
                        if (rowok && (interior || (gxp >= 0 && gxp < W))) {
                            float d1 = __fadd_rn(t0, -t2);
                            float d2 = __fadd_rn(m0, -m2);
                            float d3 = __fadd_rn(b0, -b2);
                            gxv = __fadd_rn(__fmaf_rn(2.0f, d2, d1), d3);
                            float ta = __fadd_rn(__fmaf_rn(2.0f, t1, t0), t2);
                            float tb = __fadd_rn(__fmaf_rn(2.0f, b1, b0), b2);
                            gyv = __fadd_rn(ta, -tb);
                            mag = sqrtf(__fmaf_rn(gxv, gxv, __fmul_rn(gyv, gyv)));
                        }
                        if (c == 0) { amag[0][k] = mag;  agx[0][k] = gxv;  agy[0][k] = gyv; }
                        else {
                            amag[0][k] = __fadd_rn(amag[0][k], mag);
                            agx[0][k]  = __fadd_rn(agx[0][k], gxv);
                            agy[0][k]  = __fadd_rn(agy[0][k], gyv);
                        }
                    }
                    // column 1
                    {
                        float t0 = T01.y, t1 = T23.x, t2 = T23.y;
                        float m0 = M01.y,              m2 = M23.y;
                        float b0 = B01.y, b1 = B23.x, b2 = B23.y;
                        int gxp = x0 + cc;   // x0 - 1 + (cc+1)
                        float mag = 0.0f, gxv = 0.0f, gyv = 0.0f;
                        if (rowok && (interior || (gxp >= 0 && gxp < W))) {
                            float d1 = __fadd_rn(t0, -t2);
                            float d2 = __fadd_rn(m0, -m2);
                            float d3 = __fadd_rn(b0, -b2);
                            gxv = __fadd_rn(__fmaf_rn(2.0f, d2, d1), d3);
                            float ta = __fadd_rn(__fmaf_rn(2.0f, t1, t0), t2);
                            float tb = __fadd_rn(__fmaf_rn(2.0f, b1, b0), b2);
                            gyv = __fadd_rn(ta, -tb);
                            mag = sqrtf(__fmaf_rn(gxv, gxv, __fmul_rn(gyv, gyv)));
                        }
                        if (c == 0) { amag[1][k] = mag;  agx[1][k] = gxv;  agy[1][k] = gyv; }
                        else {
                            amag[1][k] = __fadd_rn(amag[1][k], mag);
                            agx[1][k]  = __fadd_rn(agx[1][k], gxv);
                            agy[1][k]  = __fadd_rn(agy[1][k], gyv);
                        }
                    }
                    T01 = M01; T23 = M23;
                    M01 = B01; M23 = B23;
                }
            }
        }
        // write summed grad-mag (paired float2 stores)
        #pragma unroll
        for (int k = 0; k < 3; ++k) {
            int r = r0 + k;
            if (r < rend)
                *(float2*)(&s_gmag[r * GM_STR + cc]) = make_float2(amag[0][k], amag[1][k]);
        }
    }
    __syncthreads();

    // ================= NMS + threshold: octant classification (R15-proven) =================
    const float T1 = 0.41421320f;
    const float T2 = 2.41420674f;
    if (tid < 204) {
        #pragma unroll
        for (int j = 0; j < 2; ++j) {
            int col = dcc + j;
            if (col >= 1 && col <= TS) {
                #pragma unroll
                for (int k = 0; k < 3; ++k) {
                    int r = r0 + k;
                    if (r < rend && r >= 1 && r <= TS) {
                        float gm = amag[j][k];
                        float X = agx[j][k], Y = agy[j][k];
                        float ax = fabsf(X), ay = fabsf(Y);
                        int a;
                        if (ay <= __fmul_rn(T1, ax))      a = 0;
                        else if (ay >= __fmul_rn(T2, ax)) a = 2;
                        else a = ((__float_as_int(X) ^ __float_as_int(Y)) >= 0) ? 1 : 3;
                        int ci = r * GM_STR + col;
                        float pos = __fadd_rn(gm, -s_gmag[ci + s_noff[a]]);
                        float neg = __fadd_rn(gm, -s_gmag[ci + s_noff[a + 4]]);
                        float thin = (fminf(pos, neg) > 0.0f) ? gm : 0.0f;
                        float res = (thin < 10.0f) ? 0.0f : thin;
                        out[((size_t)b * H + (y0 + r - 1)) * W + (x0 + col - 1)] = res;
                    }
                }
            }
        }
    }
}

extern "C" void kernel_launch(void* const* d_in, const int* in_sizes, int n_in,
                              void* d_out, int out_size)
{
    const float* img = (const float*)d_in[0];
    float* out = (float*)d_out;
    const int H = 512, W = 512;
    int B = in_sizes[0] / (3 * H * W);   // 16
    dim3 grid(W / TS, H / TS, B);
    canny_fused_kernel<<<grid, NT>>>(img, out, H, W);
}